// round 17
// baseline (speedup 1.0000x reference)
#include <cuda_runtime.h>
#include <math.h>
#include <cstdint>

#define NN 50000
#define EE 800000
#define ET 850000        // EE + NN self loops
#define FNEG 0.2f

// ---------------- static device scratch (no allocation allowed) ----------------
__device__ float g_xw [NN * 128];    // per-layer x@W (layer2: [N,12])
__device__ float g_acc[NN * 128];    // linear part
__device__ float g_h  [NN * 128];    // activations between layers
__device__ float g_als[NN * 6];
__device__ float g_ald[NN * 6];
__device__ float g_ebuf[5100000];    // ET * 6 edge exp values
__device__ float g_lin2[NN * 2];     // layer2 linear part
// CSR by destination
__device__ int g_cnt[NN];
__device__ int g_rowptr[NN + 1];
__device__ int g_woff[NN];
__device__ int g_csrc[ET];

// ---------------- helpers ----------------
__device__ __forceinline__ uint32_t f2tf(float f) {
    uint32_t r;
    asm("cvt.rna.tf32.f32 %0, %1;" : "=r"(r) : "f"(f));
    return r;
}

// ================= CSR build (counting sort by dst) ============================
__global__ void csr_zero() {
    int t = blockIdx.x * blockDim.x + threadIdx.x;
    if (t < NN) g_cnt[t] = 0;
}
__global__ void csr_hist(const int *__restrict__ ei) {
    int e0 = (blockIdx.x * blockDim.x + threadIdx.x) * 8;
    if (e0 + 7 < EE) {
        int4 d0 = *(const int4 *)(ei + EE + e0);
        int4 d1 = *(const int4 *)(ei + EE + e0 + 4);
        atomicAdd(&g_cnt[d0.x], 1); atomicAdd(&g_cnt[d0.y], 1);
        atomicAdd(&g_cnt[d0.z], 1); atomicAdd(&g_cnt[d0.w], 1);
        atomicAdd(&g_cnt[d1.x], 1); atomicAdd(&g_cnt[d1.y], 1);
        atomicAdd(&g_cnt[d1.z], 1); atomicAdd(&g_cnt[d1.w], 1);
    } else {
#pragma unroll
        for (int u = 0; u < 8; u++) {
            int e = e0 + u;
            if (e < ET) {
                int dst = (e < EE) ? ei[EE + e] : (e - EE);
                atomicAdd(&g_cnt[dst], 1);
            }
        }
    }
}
__global__ __launch_bounds__(1024) void csr_scan() {
    __shared__ int partial[1024];
    const int CH = (NN + 1023) / 1024;
    int t = threadIdx.x;
    int start = t * CH;
    int s = 0;
#pragma unroll 7
    for (int i = 0; i < CH; i++) {
        int idx = start + i;
        if (idx < NN) s += g_cnt[idx];
    }
    partial[t] = s;
    __syncthreads();
    for (int off = 1; off < 1024; off <<= 1) {
        int u = (t >= off) ? partial[t - off] : 0;
        __syncthreads();
        partial[t] += u;
        __syncthreads();
    }
    int run = partial[t] - s;
    for (int i = 0; i < CH; i++) {
        int idx = start + i;
        if (idx < NN) {
            g_rowptr[idx] = run;
            g_woff[idx] = run;
            run += g_cnt[idx];
        }
    }
    if (t == 0) g_rowptr[NN] = ET;
}
__global__ void csr_scatter(const int *__restrict__ ei) {
    int e0 = (blockIdx.x * blockDim.x + threadIdx.x) * 8;
    if (e0 + 7 < EE) {
        int4 s0 = *(const int4 *)(ei + e0);
        int4 s1 = *(const int4 *)(ei + e0 + 4);
        int4 d0 = *(const int4 *)(ei + EE + e0);
        int4 d1 = *(const int4 *)(ei + EE + e0 + 4);
        int p0 = atomicAdd(&g_woff[d0.x], 1);
        int p1 = atomicAdd(&g_woff[d0.y], 1);
        int p2 = atomicAdd(&g_woff[d0.z], 1);
        int p3 = atomicAdd(&g_woff[d0.w], 1);
        int p4 = atomicAdd(&g_woff[d1.x], 1);
        int p5 = atomicAdd(&g_woff[d1.y], 1);
        int p6 = atomicAdd(&g_woff[d1.z], 1);
        int p7 = atomicAdd(&g_woff[d1.w], 1);
        g_csrc[p0] = s0.x; g_csrc[p1] = s0.y; g_csrc[p2] = s0.z; g_csrc[p3] = s0.w;
        g_csrc[p4] = s1.x; g_csrc[p5] = s1.y; g_csrc[p6] = s1.z; g_csrc[p7] = s1.w;
    } else {
#pragma unroll
        for (int u = 0; u < 8; u++) {
            int e = e0 + u;
            if (e < ET) {
                int src, dst;
                if (e < EE) { src = ei[e]; dst = ei[EE + e]; }
                else        { src = dst = e - EE; }
                int pos = atomicAdd(&g_woff[dst], 1);
                g_csrc[pos] = src;
            }
        }
    }
}

// ======= tf32 mma.sync GEMM: C[N,128] = A[N,128] @ B[128,128] (+fused logits) ==
// blockIdx.y == 0: B=B0, C=g_xw, epilogue computes g_als/g_ald
// blockIdx.y == 1: B=B1, C=g_acc
// Block: 128x128 tile, 8 warps in 2(m) x 4(n); warp tile 64x32.
__global__ __launch_bounds__(256) void gemm_mma(const float *__restrict__ Ain,
                                                const float *__restrict__ B0,
                                                const float *__restrict__ B1,
                                                int srcX,
                                                const float *__restrict__ a_s,
                                                const float *__restrict__ a_d) {
    const float *A = srcX ? Ain : g_h;
    const float *B = (blockIdx.y == 0) ? B0 : B1;
    float *C       = (blockIdx.y == 0) ? g_xw : g_acc;
    bool doLog     = (blockIdx.y == 0);

    __shared__ uint32_t As[128][20];    // [row][k] pad->20 (conflict-free frag reads)
    __shared__ uint32_t Bs[16][136];    // [k][col] pad->136

    int tid = threadIdx.x, wid = tid >> 5, lane = tid & 31;
    int warp_m = wid >> 2;              // 0..1  -> rows warp_m*64
    int warp_n = wid & 3;               // 0..3  -> cols warp_n*32 (== head)
    int rowBase = blockIdx.x * 128;
    int g4 = lane >> 2, l4 = lane & 3;  // groupID, thread-in-group

    float acc[4][4][4];
#pragma unroll
    for (int mt = 0; mt < 4; mt++)
#pragma unroll
        for (int nt = 0; nt < 4; nt++)
#pragma unroll
            for (int q = 0; q < 4; q++) acc[mt][nt][q] = 0.f;

    for (int k0 = 0; k0 < 128; k0 += 16) {
        // stage A: 128 rows x 16 k
#pragma unroll
        for (int t = 0; t < 2; t++) {
            int idx = tid + t * 256;
            int r = idx >> 2, kq = idx & 3;
            int grow = rowBase + r;
            float4 v = make_float4(0.f, 0.f, 0.f, 0.f);
            if (grow < NN) v = *(const float4 *)(A + grow * 128 + k0 + kq * 4);
            As[r][kq * 4 + 0] = f2tf(v.x);
            As[r][kq * 4 + 1] = f2tf(v.y);
            As[r][kq * 4 + 2] = f2tf(v.z);
            As[r][kq * 4 + 3] = f2tf(v.w);
        }
        // stage B: 16 k x 128 n
#pragma unroll
        for (int t = 0; t < 2; t++) {
            int idx = tid + t * 256;
            int r = idx >> 5, cq = idx & 31;
            float4 v = *(const float4 *)(B + (k0 + r) * 128 + cq * 4);
            Bs[r][cq * 4 + 0] = f2tf(v.x);
            Bs[r][cq * 4 + 1] = f2tf(v.y);
            Bs[r][cq * 4 + 2] = f2tf(v.z);
            Bs[r][cq * 4 + 3] = f2tf(v.w);
        }
        __syncthreads();
#pragma unroll
        for (int kc = 0; kc < 16; kc += 8) {
            uint32_t bf0[4], bf1[4];
#pragma unroll
            for (int nt = 0; nt < 4; nt++) {
                int col = warp_n * 32 + nt * 8 + g4;
                bf0[nt] = Bs[kc + l4][col];
                bf1[nt] = Bs[kc + l4 + 4][col];
            }
#pragma unroll
            for (int mt = 0; mt < 4; mt++) {
                int r = warp_m * 64 + mt * 16 + g4;
                uint32_t a0 = As[r][kc + l4];
                uint32_t a1 = As[r + 8][kc + l4];
                uint32_t a2 = As[r][kc + l4 + 4];
                uint32_t a3 = As[r + 8][kc + l4 + 4];
#pragma unroll
                for (int nt = 0; nt < 4; nt++) {
                    asm("mma.sync.aligned.m16n8k8.row.col.f32.tf32.tf32.f32 "
                        "{%0,%1,%2,%3}, {%4,%5,%6,%7}, {%8,%9}, {%0,%1,%2,%3};"
                        : "+f"(acc[mt][nt][0]), "+f"(acc[mt][nt][1]),
                          "+f"(acc[mt][nt][2]), "+f"(acc[mt][nt][3])
                        : "r"(a0), "r"(a1), "r"(a2), "r"(a3),
                          "r"(bf0[nt]), "r"(bf1[nt]));
                }
            }
        }
        __syncthreads();
    }

    // epilogue: store C; fused attention logits (head = warp_n)
    float asub[8], dsub[8];
    if (doLog) {
#pragma unroll
        for (int nt = 0; nt < 4; nt++) {
            int hc = nt * 8 + 2 * l4;
            asub[nt * 2 + 0] = a_s[warp_n * 32 + hc];
            asub[nt * 2 + 1] = a_s[warp_n * 32 + hc + 1];
            dsub[nt * 2 + 0] = a_d[warp_n * 32 + hc];
            dsub[nt * 2 + 1] = a_d[warp_n * 32 + hc + 1];
        }
    }
#pragma unroll
    for (int mt = 0; mt < 4; mt++) {
        int row0 = rowBase + warp_m * 64 + mt * 16 + g4;
        int row1 = row0 + 8;
        float ps0 = 0.f, pd0 = 0.f, ps1 = 0.f, pd1 = 0.f;
#pragma unroll
        for (int nt = 0; nt < 4; nt++) {
            int col = warp_n * 32 + nt * 8 + 2 * l4;
            float c0 = acc[mt][nt][0], c1 = acc[mt][nt][1];
            float c2 = acc[mt][nt][2], c3 = acc[mt][nt][3];
            if (row0 < NN) *(float2 *)(C + row0 * 128 + col) = make_float2(c0, c1);
            if (row1 < NN) *(float2 *)(C + row1 * 128 + col) = make_float2(c2, c3);
            if (doLog) {
                ps0 += c0 * asub[nt * 2] + c1 * asub[nt * 2 + 1];
                pd0 += c0 * dsub[nt * 2] + c1 * dsub[nt * 2 + 1];
                ps1 += c2 * asub[nt * 2] + c3 * asub[nt * 2 + 1];
                pd1 += c2 * dsub[nt * 2] + c3 * dsub[nt * 2 + 1];
            }
        }
        if (doLog) {
            ps0 += __shfl_xor_sync(0xffffffffu, ps0, 1);
            ps0 += __shfl_xor_sync(0xffffffffu, ps0, 2);
            pd0 += __shfl_xor_sync(0xffffffffu, pd0, 1);
            pd0 += __shfl_xor_sync(0xffffffffu, pd0, 2);
            ps1 += __shfl_xor_sync(0xffffffffu, ps1, 1);
            ps1 += __shfl_xor_sync(0xffffffffu, ps1, 2);
            pd1 += __shfl_xor_sync(0xffffffffu, pd1, 1);
            pd1 += __shfl_xor_sync(0xffffffffu, pd1, 2);
            if (l4 == 0) {
                if (row0 < NN) { g_als[row0 * 4 + warp_n] = ps0; g_ald[row0 * 4 + warp_n] = pd0; }
                if (row1 < NN) { g_als[row1 * 4 + warp_n] = ps1; g_ald[row1 * 4 + warp_n] = pd1; }
            }
        }
    }
}

// ------------- layer2 logits (H=6, C=2) ----------------------------------------
__global__ void logits2(const float *__restrict__ a_s, const float *__restrict__ a_d) {
    int t = blockIdx.x * blockDim.x + threadIdx.x;
    if (t >= NN * 6) return;
    int n = t / 6, h = t - n * 6;
    float x0 = g_xw[n * 12 + h * 2], x1 = g_xw[n * 12 + h * 2 + 1];
    g_als[t] = x0 * a_s[h * 2] + x1 * a_s[h * 2 + 1];
    g_ald[t] = x0 * a_d[h * 2] + x1 * a_d[h * 2 + 1];
}

// ============ fused node pass (layers 0/1): softmax + gather + relu ============
__global__ __launch_bounds__(256) void nodepass01(const float *__restrict__ cb,
                                                  const float *__restrict__ lb) {
    int w = (blockIdx.x * blockDim.x + threadIdx.x) >> 5;
    int lane = threadIdx.x & 31;
    if (w >= NN) return;
    int base = g_rowptr[w];
    int deg  = g_rowptr[w + 1] - base;

    int h4 = lane & 3;
    float ald_h = g_ald[w * 4 + h4];
    float mx = __int_as_float(0xFF800000);
    float sum = 0.f;

    if (deg <= 64) {
        float areg[8];
        int i = 0;
        for (int k = lane >> 2; k < deg; k += 8, i++) {
            int src = g_csrc[base + k];
            float a = g_als[src * 4 + h4] + ald_h;
            a = a > 0.f ? a : FNEG * a;
            areg[i] = a;
            mx = fmaxf(mx, a);
        }
        mx = fmaxf(mx, __shfl_xor_sync(0xffffffffu, mx, 4));
        mx = fmaxf(mx, __shfl_xor_sync(0xffffffffu, mx, 8));
        mx = fmaxf(mx, __shfl_xor_sync(0xffffffffu, mx, 16));
        i = 0;
        for (int k = lane >> 2; k < deg; k += 8, i++) {
            float e = __expf(areg[i] - mx);
            g_ebuf[(base + k) * 4 + h4] = e;
            sum += e;
        }
    } else {
        for (int k = lane >> 2; k < deg; k += 8) {
            int src = g_csrc[base + k];
            float a = g_als[src * 4 + h4] + ald_h;
            a = a > 0.f ? a : FNEG * a;
            g_ebuf[(base + k) * 4 + h4] = a;
            mx = fmaxf(mx, a);
        }
        mx = fmaxf(mx, __shfl_xor_sync(0xffffffffu, mx, 4));
        mx = fmaxf(mx, __shfl_xor_sync(0xffffffffu, mx, 8));
        mx = fmaxf(mx, __shfl_xor_sync(0xffffffffu, mx, 16));
        for (int k = lane >> 2; k < deg; k += 8) {
            float a = g_ebuf[(base + k) * 4 + h4];
            float e = __expf(a - mx);
            g_ebuf[(base + k) * 4 + h4] = e;
            sum += e;
        }
    }
    sum += __shfl_xor_sync(0xffffffffu, sum, 4);
    sum += __shfl_xor_sync(0xffffffffu, sum, 8);
    sum += __shfl_xor_sync(0xffffffffu, sum, 16);
    float inv = 1.f / sum;
    __syncwarp();

    int hc = lane >> 3;
    float cinv = __shfl_sync(0xffffffffu, inv, hc);
    float4 acc = make_float4(0.f, 0.f, 0.f, 0.f);
    int k = 0;
    for (; k + 3 < deg; k += 4) {
        int s0 = g_csrc[base + k],     s1 = g_csrc[base + k + 1];
        int s2 = g_csrc[base + k + 2], s3 = g_csrc[base + k + 3];
        float e0 = g_ebuf[(base + k) * 4 + hc];
        float e1 = g_ebuf[(base + k + 1) * 4 + hc];
        float e2 = g_ebuf[(base + k + 2) * 4 + hc];
        float e3 = g_ebuf[(base + k + 3) * 4 + hc];
        float4 v0 = *(const float4 *)(g_xw + s0 * 128 + lane * 4);
        float4 v1 = *(const float4 *)(g_xw + s1 * 128 + lane * 4);
        float4 v2 = *(const float4 *)(g_xw + s2 * 128 + lane * 4);
        float4 v3 = *(const float4 *)(g_xw + s3 * 128 + lane * 4);
        float c0 = e0 * cinv, c1 = e1 * cinv, c2 = e2 * cinv, c3 = e3 * cinv;
        acc.x += c0 * v0.x + c1 * v1.x + c2 * v2.x + c3 * v3.x;
        acc.y += c0 * v0.y + c1 * v1.y + c2 * v2.y + c3 * v3.y;
        acc.z += c0 * v0.z + c1 * v1.z + c2 * v2.z + c3 * v3.z;
        acc.w += c0 * v0.w + c1 * v1.w + c2 * v2.w + c3 * v3.w;
    }
    for (; k < deg; k++) {
        int s0 = g_csrc[base + k];
        float e0 = g_ebuf[(base + k) * 4 + hc];
        float4 v0 = *(const float4 *)(g_xw + s0 * 128 + lane * 4);
        float c0 = e0 * cinv;
        acc.x += c0 * v0.x; acc.y += c0 * v0.y;
        acc.z += c0 * v0.z; acc.w += c0 * v0.w;
    }

    int c = lane * 4;
    float4 lin = *(const float4 *)(g_acc + w * 128 + c);
    float4 b0 = *(const float4 *)(cb + c);
    float4 b1 = *(const float4 *)(lb + c);
    float4 o;
    o.x = acc.x + lin.x + b0.x + b1.x;
    o.y = acc.y + lin.y + b0.y + b1.y;
    o.z = acc.z + lin.z + b0.z + b1.z;
    o.w = acc.w + lin.w + b0.w + b1.w;
    o.x = o.x > 0.f ? o.x : 0.f;
    o.y = o.y > 0.f ? o.y : 0.f;
    o.z = o.z > 0.f ? o.z : 0.f;
    o.w = o.w > 0.f ? o.w : 0.f;
    *(float4 *)(g_h + w * 128 + c) = o;
}

// ============ fused node pass (layer 2, H=6, C=2, concat=False) ================
__global__ __launch_bounds__(256) void nodepass2(const float *__restrict__ cb,
                                                 const float *__restrict__ lb,
                                                 float *__restrict__ out) {
    int w = (blockIdx.x * blockDim.x + threadIdx.x) >> 5;
    int lane = threadIdx.x & 31;
    if (w >= NN) return;
    int base = g_rowptr[w];
    int deg  = g_rowptr[w + 1] - base;

    int h8 = lane & 7;
    bool hact = h8 < 6;
    float ald_h = hact ? g_ald[w * 6 + h8] : 0.f;
    float mx = __int_as_float(0xFF800000);
    for (int k = lane >> 3; k < deg; k += 4) {
        int src = g_csrc[base + k];
        if (hact) {
            float a = g_als[src * 6 + h8] + ald_h;
            a = a > 0.f ? a : FNEG * a;
            g_ebuf[(base + k) * 6 + h8] = a;
            mx = fmaxf(mx, a);
        }
    }
    mx = fmaxf(mx, __shfl_xor_sync(0xffffffffu, mx, 8));
    mx = fmaxf(mx, __shfl_xor_sync(0xffffffffu, mx, 16));
    float sum = 0.f;
    for (int k = lane >> 3; k < deg; k += 4) {
        if (hact) {
            float a = g_ebuf[(base + k) * 6 + h8];
            float e = __expf(a - mx);
            g_ebuf[(base + k) * 6 + h8] = e;
            sum += e;
        }
    }
    sum += __shfl_xor_sync(0xffffffffu, sum, 8);
    sum += __shfl_xor_sync(0xffffffffu, sum, 16);
    float inv = (hact && sum != 0.f) ? 1.f / sum : 0.f;
    __syncwarp();

    // phase 3: lanes 0..23 -> 2 edges in flight (lanes 12..23 take edge k+1);
    // within each 12-lane group: head = sl>>1, out-col = sl&1
    bool act = lane < 24;
    int sl = act ? (lane >= 12 ? lane - 12 : lane) : 0;
    int ke = (act && lane >= 12) ? 1 : 0;
    float cinv = __shfl_sync(0xffffffffu, inv, sl >> 1);
    float acc = 0.f;
    for (int k = 0; k < deg; k += 4) {
        int kk0 = k + ke, kk1 = k + 2 + ke;
        int s0 = -1, s1 = -1;
        float e0 = 0.f, e1 = 0.f;
        if (act && kk0 < deg) {
            s0 = g_csrc[base + kk0];
            e0 = g_ebuf[(base + kk0) * 6 + (sl >> 1)];
        }
        if (act && kk1 < deg) {
            s1 = g_csrc[base + kk1];
            e1 = g_ebuf[(base + kk1) * 6 + (sl >> 1)];
        }
        if (s0 >= 0) acc += e0 * cinv * g_xw[s0 * 12 + sl];
        if (s1 >= 0) acc += e1 * cinv * g_xw[s1 * 12 + sl];
    }
    // fold the k+1 half onto lanes 0..11
    float up = __shfl_down_sync(0xffffffffu, acc, 12);
    float s = (lane < 12) ? (acc + up) : 0.f;
    // mean over 6 heads: sum lanes {o, o+2, ..., o+10} into lanes 0/1
    s += __shfl_down_sync(0xffffffffu, s, 2);
    s += __shfl_down_sync(0xffffffffu, s, 4);
    s += __shfl_down_sync(0xffffffffu, s, 8);
    if (lane < 2)
        out[w * 2 + lane] = s * (1.f / 6.f) + cb[lane] + g_lin2[w * 2 + lane] + lb[lane];
}

// ------------- layer2 small GEMM: g_xw[N,12] = h@c2_W ; g_lin2[N,2] = h@l2_W ---
__global__ __launch_bounds__(256) void gemm_l2(const float *__restrict__ c2W,
                                               const float *__restrict__ l2W) {
    __shared__ float Ah[64][128];
    __shared__ float Ws[128 * 14];
    int tid = threadIdx.x;
    int n0 = blockIdx.x * 64;
    for (int i = tid; i < 128 * 12; i += 256) Ws[(i / 12) * 14 + (i % 12)] = c2W[i];
    for (int i = tid; i < 128 * 2;  i += 256) Ws[(i / 2) * 14 + 12 + (i % 2)] = l2W[i];
#pragma unroll
    for (int t = 0; t < 8; t++) {
        int idx = tid + t * 256;
        int r = idx >> 5, q = idx & 31;
        int n = n0 + r;
        float4 v = make_float4(0.f, 0.f, 0.f, 0.f);
        if (n < NN) v = *(const float4 *)(g_h + n * 128 + q * 4);
        *((float4 *)&Ah[r][q * 4]) = v;
    }
    __syncthreads();
    for (int o = tid; o < 64 * 14; o += 256) {
        int r = o / 14, col = o - r * 14;
        int n = n0 + r;
        if (n >= NN) continue;
        float s = 0.f;
#pragma unroll
        for (int k = 0; k < 128; k++) s += Ah[r][k] * Ws[k * 14 + col];
        if (col < 12) g_xw[n * 12 + col] = s;
        else          g_lin2[n * 2 + (col - 12)] = s;
    }
}

// ---------------- launch --------------------------------------------------------
extern "C" void kernel_launch(void *const *d_in, const int *in_sizes, int n_in,
                              void *d_out, int out_size) {
    const float *x   = (const float *)d_in[0];
    const int   *ei  = (const int *)d_in[1];
    // d_in[2] edge_attr: ignored (GATConv edge_dim=None)
    const float *c0W = (const float *)d_in[3],  *c0as = (const float *)d_in[4];
    const float *c0ad= (const float *)d_in[5],  *c0b  = (const float *)d_in[6];
    const float *l0W = (const float *)d_in[7],  *l0b  = (const float *)d_in[8];
    const float *c1W = (const float *)d_in[9],  *c1as = (const float *)d_in[10];
    const float *c1ad= (const float *)d_in[11], *c1b  = (const float *)d_in[12];
    const float *l1W = (const float *)d_in[13], *l1b  = (const float *)d_in[14];
    const float *c2W = (const float *)d_in[15], *c2as = (const float *)d_in[16];
    const float *c2ad= (const float *)d_in[17], *c2b  = (const float *)d_in[18];
    const float *l2W = (const float *)d_in[19], *l2b  = (const float *)d_in[20];
    float *out = (float *)d_out;

    dim3 gg((NN + 127) / 128, 2);
    int gN6 = (NN * 6 + 255) / 256;
    int gE8 = (ET + 2047) / 2048;       // 8 edges per thread
    int gNW = (NN * 32 + 255) / 256;    // one warp per node

    // ---- CSR build (edge structure shared by all layers) ----
    csr_zero<<<(NN + 255) / 256, 256>>>();
    csr_hist<<<gE8, 256>>>(ei);
    csr_scan<<<1, 1024>>>();
    csr_scatter<<<gE8, 256>>>(ei);

    // ---- layer 0 ----
    gemm_mma<<<gg, 256>>>(x, c0W, l0W, 1, c0as, c0ad);
    nodepass01<<<gNW, 256>>>(c0b, l0b);

    // ---- layer 1 ----
    gemm_mma<<<gg, 256>>>(x, c1W, l1W, 0, c1as, c1ad);
    nodepass01<<<gNW, 256>>>(c1b, l1b);

    // ---- layer 2 ----
    gemm_l2<<<(NN + 63) / 64, 256>>>(c2W, l2W);
    logits2<<<gN6, 256>>>(c2as, c2ad);
    nodepass2<<<gNW, 256>>>(c2b, l2b, out);
}